// round 8
// baseline (speedup 1.0000x reference)
#include <cuda_runtime.h>
#include <cstdint>

// BidPrefix: row = [rates[0..299], market_price, bid]
//   cp1[j] = prod_{k<j} rates[k]
//   out[0:B]  = cp1[bid]            (bid in [0,300])
//   out[B:2B] = cp1[mp] - cp1[mp+1] (mp  in [0,299])
//
// One warp per TWO rows (software pipelining to hide the tail->predicated-load
// serial chain). Interleaved ownership: lane t holds float2 chunks #(t+32k).
// Wave 1 (MLP=6): both tails + rounds 0,1 of both rows, unconditional.
// Wave 2: rounds 2,3,4 of both rows, predicated on maxf2 = max(bid-1,mp)>>1
// (traffic early-exit at sector granularity); skipped chunks = (1,1) and are
// never referenced by any query (all query factors have index <= maxelem).
// cp1[x], x = 64q + r (warp-uniform):
//   m_t = c_q[t] * (2t<r ? vx_q : 1) * (2t+1<r ? vy_q : 1);  butterfly-product.
// Four butterfly chains (2 queries x 2 rows) interleaved in one loop.

static constexpr int ROW   = 302;
static constexpr int WARPS = 4;               // 128-thread blocks
static constexpr unsigned FULL = 0xffffffffu;

struct QPre { float m, vx, vy; };             // pre-butterfly value + round-q pair

__device__ __forceinline__ QPre qpre(int x, int lane2,
                                     const float2& v0, const float2& v1,
                                     const float2& v2, const float2& v3,
                                     const float2& v4,
                                     float c1, float c2, float c3, float c4)
{
    const int q = x >> 6, r = x & 63;         // warp-uniform
    float cq = 1.0f;
    cq = (q == 1) ? c1 : cq;
    cq = (q == 2) ? c2 : cq;
    cq = (q == 3) ? c3 : cq;
    cq = (q == 4) ? c4 : cq;
    float vx = v0.x, vy = v0.y;
    vx = (q == 1) ? v1.x : vx;  vy = (q == 1) ? v1.y : vy;
    vx = (q == 2) ? v2.x : vx;  vy = (q == 2) ? v2.y : vy;
    vx = (q == 3) ? v3.x : vx;  vy = (q == 3) ? v3.y : vy;
    vx = (q == 4) ? v4.x : vx;  vy = (q == 4) ? v4.y : vy;
    float m = cq;
    m *= (lane2     < r) ? vx : 1.0f;
    m *= (lane2 + 1 < r) ? vy : 1.0f;
    return {m, vx, vy};
}

__global__ __launch_bounds__(128) void bidprefix_kernel(
    const float* __restrict__ in, float* __restrict__ out, int batch)
{
    const int wib  = threadIdx.x >> 5;
    const int lane = threadIdx.x & 31;
    const int w    = blockIdx.x * WARPS + wib;
    const int r0   = 2 * w;
    if (r0 >= batch) return;
    const int r1   = r0 + 1;
    const bool hasB = (r1 < batch);

    const float2* A = reinterpret_cast<const float2*>(in + (size_t)r0 * ROW);
    const float2* B = reinterpret_cast<const float2*>(in + (size_t)(hasB ? r1 : r0) * ROW);

    // wave 1: independent, MLP = 6
    const float2 tA = A[150];
    const float2 tB = B[150];
    const float2 a0 = A[lane];       const float2 a1 = A[lane + 32];
    const float2 b0 = B[lane];       const float2 b1 = B[lane + 32];

    const int mpA = (int)tA.x, bidA = (int)tA.y;
    const int mpB = (int)tB.x, bidB = (int)tB.y;
    const int mfA = max(bidA - 1, mpA) >> 1;   // last float2 chunk needed, row A
    const int mfB = max(bidB - 1, mpB) >> 1;

    // wave 2: predicated early-exit loads (latency hidden by sibling row)
    const float2 one = make_float2(1.0f, 1.0f);
    float2 a2 = one, a3 = one, a4 = one;
    float2 b2 = one, b3 = one, b4 = one;
    if (lane +  64 <= mfA) a2 = A[lane +  64];
    if (lane +  96 <= mfA) a3 = A[lane +  96];
    if (lane + 128 <= mfA) a4 = A[lane + 128];
    if (lane +  64 <= mfB) b2 = B[lane +  64];
    if (lane +  96 <= mfB) b3 = B[lane +  96];
    if (lane + 128 <= mfB) b4 = B[lane + 128];

    // vertical chains: c_j = prod over rounds < j of (vx*vy)
    const float cA1 = a0.x * a0.y;
    const float cA2 = cA1 * (a1.x * a1.y);
    const float cA3 = cA2 * (a2.x * a2.y);
    const float cA4 = cA3 * (a3.x * a3.y);
    const float cB1 = b0.x * b0.y;
    const float cB2 = cB1 * (b1.x * b1.y);
    const float cB3 = cB2 * (b2.x * b2.y);
    const float cB4 = cB3 * (b3.x * b3.y);

    const int lane2 = 2 * lane;

    QPre sA = qpre(bidA, lane2, a0, a1, a2, a3, a4, cA1, cA2, cA3, cA4);
    QPre pA = qpre(mpA,  lane2, a0, a1, a2, a3, a4, cA1, cA2, cA3, cA4);
    QPre sB = qpre(bidB, lane2, b0, b1, b2, b3, b4, cB1, cB2, cB3, cB4);
    QPre pB = qpre(mpB,  lane2, b0, b1, b2, b3, b4, cB1, cB2, cB3, cB4);

    float m1A = sA.m, m2A = pA.m, m1B = sB.m, m2B = pB.m;
    #pragma unroll
    for (int off = 16; off; off >>= 1) {       // 4 chains pipeline SHFL latency
        const float u1 = __shfl_xor_sync(FULL, m1A, off);
        const float u2 = __shfl_xor_sync(FULL, m2A, off);
        const float u3 = __shfl_xor_sync(FULL, m1B, off);
        const float u4 = __shfl_xor_sync(FULL, m2B, off);
        m1A *= u1;  m2A *= u2;  m1B *= u3;  m2B *= u4;
    }
    // m1* = cp1[bid], m2* = cp1[mp] in every lane

    // rates[mp]: reuse mp-query's selected round pair (owner lane r>>1, parity)
    const float rselA = (mpA & 1) ? pA.vy : pA.vx;
    const float rselB = (mpB & 1) ? pB.vy : pB.vx;
    const float rmpA  = __shfl_sync(FULL, rselA, (mpA & 63) >> 1);
    const float rmpB  = __shfl_sync(FULL, rselB, (mpB & 63) >> 1);

    if (lane == 0) {
        const float lastA = m2A - m2A * rmpA;  // cp1[mp] - cp1[mp+1]
        const float lastB = m2B - m2B * rmpB;
        if (hasB) {                            // r0 even -> 8B-aligned pairs
            *reinterpret_cast<float2*>(out + r0)         = make_float2(m1A, m1B);
            *reinterpret_cast<float2*>(out + batch + r0) = make_float2(lastA, lastB);
        } else {
            out[r0]         = m1A;
            out[batch + r0] = lastA;
        }
    }
}

extern "C" void kernel_launch(void* const* d_in, const int* in_sizes, int n_in,
                              void* d_out, int out_size)
{
    const float* in  = (const float*)d_in[0];
    float*       out = (float*)d_out;
    const int batch  = in_sizes[0] / ROW;         // 500000

    const int rows_per_block = 2 * WARPS;         // 8
    const int threads = 32 * WARPS;               // 128
    const int blocks  = (batch + rows_per_block - 1) / rows_per_block;
    bidprefix_kernel<<<blocks, threads>>>(in, out, batch);
}